// round 14
// baseline (speedup 1.0000x reference)
#include <cuda_runtime.h>
#include <cuda_bf16.h>
#include <math.h>
#include <stdint.h>

#define NPT 262144
#define NMODE 2304
#define NPAIR 144
#define TWO_PI 6.283185307179586f

// ---------------- device-global scratch (no allocations allowed) -------------
// h layout: [b][pencil][i*64+z]  (16 KB contiguous tile per pencil)
__device__ float g_hA[2 * 64 * NPT];
__device__ float g_hB[2 * 64 * NPT];
__device__ __nv_bfloat162 g_Zf[2 * 4096 * 576];   // [b][p][i][kz]  (bf16 cplx)
__device__ float g_Yf[2 * 64 * 64 * 288];         // [b][i][x][(ky*9+kz)*2]
__device__ float g_Xm[2 * NMODE * 64 * 2];        // [b][m][i] complex
__device__ float g_Om[2 * 64 * NMODE * 2];        // [b][o][m] complex
__device__ __nv_bfloat162 g_IY[2 * 4096 * 576];   // [b][p][o][kz]  (bf16 cplx)
__device__ __nv_bfloat16 g_Rk[NMODE * 64 * 64];   // [m][i][o]  (bf16)
__device__ float g_bas[NMODE * 20];
__device__ float g_dec[NMODE];

// 20 polynomial terms (p,q,r) with p+q+r < 4
__device__ __constant__ int c_tp[20] = {0,0,0,0,0,0,0,0,0,0, 1,1,1,1,1,1, 2,2,2, 3};
__device__ __constant__ int c_tq[20] = {0,0,0,0,1,1,1,2,2,3, 0,0,0,1,1,2, 0,0,1, 0};
__device__ __constant__ int c_tr[20] = {0,1,2,3,0,1,2,0,1,0, 0,1,2,0,1,0, 0,1,0, 0};

__device__ __forceinline__ float gelu_exact(float v) {
    return 0.5f * v * (1.0f + erff(v * 0.70710678118654752f));
}

__device__ __forceinline__ uint32_t f2tf(float x) {
    uint32_t r;
    asm("cvt.rna.tf32.f32 %0, %1;" : "=r"(r) : "f"(x));
    return r;
}

__device__ __forceinline__ void mma_tf32(float* c, uint32_t a0, uint32_t a1,
                                         uint32_t a2, uint32_t a3,
                                         uint32_t b0, uint32_t b1) {
    asm volatile(
        "mma.sync.aligned.m16n8k8.row.col.f32.tf32.tf32.f32 "
        "{%0,%1,%2,%3}, {%4,%5,%6,%7}, {%8,%9}, {%0,%1,%2,%3};\n"
        : "+f"(c[0]), "+f"(c[1]), "+f"(c[2]), "+f"(c[3])
        : "r"(a0), "r"(a1), "r"(a2), "r"(a3), "r"(b0), "r"(b1));
}

// radix-8 real z-DFT over 64 elements -> 9 cplx. tw[z0*8+(k-1)] = e^{-2pi i z0 k/64}
__device__ __forceinline__ void zdft_radix8(const float* row, const float2* tw,
                                            float* ar, float* ai) {
#pragma unroll
    for (int k = 0; k < 9; k++) { ar[k] = 0.f; ai[k] = 0.f; }
    const float S = 0.70710678118654752f;
#pragma unroll
    for (int z0 = 0; z0 < 8; z0++) {
        float x0 = row[z0], x1 = row[z0 + 8], x2 = row[z0 + 16], x3 = row[z0 + 24];
        float x4 = row[z0 + 32], x5 = row[z0 + 40], x6 = row[z0 + 48], x7 = row[z0 + 56];
        float a0 = x0 + x4, A1 = x0 - x4;
        float a2 = x2 + x6, a3 = x2 - x6;
        float a4 = x1 + x5, a5 = x1 - x5;
        float a6 = x3 + x7, a7 = x3 - x7;
        float b0 = a0 + a2, b1 = a4 + a6;
        float F0  = b0 + b1, F4 = b0 - b1;
        float F2r = a0 - a2, F2i = -(a4 - a6);
        float u = S * (a5 - a7), v = S * (a5 + a7);
        float F1r = A1 + u, F1i = -(a3 + v);
        float F3r = A1 - u, F3i = a3 - v;
        const float2* w = tw + z0 * 8;
        ar[0] += F0;
        { float2 W = w[0]; ar[1] = fmaf(F1r, W.x, fmaf(-F1i, W.y, ar[1])); ai[1] = fmaf(F1r, W.y, fmaf(F1i, W.x, ai[1])); }
        { float2 W = w[1]; ar[2] = fmaf(F2r, W.x, fmaf(-F2i, W.y, ar[2])); ai[2] = fmaf(F2r, W.y, fmaf(F2i, W.x, ai[2])); }
        { float2 W = w[2]; ar[3] = fmaf(F3r, W.x, fmaf(-F3i, W.y, ar[3])); ai[3] = fmaf(F3r, W.y, fmaf(F3i, W.x, ai[3])); }
        { float2 W = w[3]; ar[4] = fmaf(F4,  W.x, ar[4]); ai[4] = fmaf(F4, W.y, ai[4]); }
        { float2 W = w[4]; ar[5] = fmaf(F3r, W.x, fmaf( F3i, W.y, ar[5])); ai[5] = fmaf(F3r, W.y, fmaf(-F3i, W.x, ai[5])); }
        { float2 W = w[5]; ar[6] = fmaf(F2r, W.x, fmaf( F2i, W.y, ar[6])); ai[6] = fmaf(F2r, W.y, fmaf(-F2i, W.x, ai[6])); }
        { float2 W = w[6]; ar[7] = fmaf(F1r, W.x, fmaf( F1i, W.y, ar[7])); ai[7] = fmaf(F1r, W.y, fmaf(-F1i, W.x, ai[7])); }
        { float2 W = w[7]; ar[8] = fmaf(F0,  W.x, ar[8]); ai[8] = fmaf(F0, W.y, ai[8]); }
    }
}

// expand uint4 (8 bf16) into 8 floats at dst
__device__ __forceinline__ void bf8_to_f8(uint4 v, float* dst) {
    float2 f;
    f = __bfloat1622float2(*(__nv_bfloat162*)&v.x); dst[0] = f.x; dst[1] = f.y;
    f = __bfloat1622float2(*(__nv_bfloat162*)&v.y); dst[2] = f.x; dst[3] = f.y;
    f = __bfloat1622float2(*(__nv_bfloat162*)&v.z); dst[4] = f.x; dst[5] = f.y;
    f = __bfloat1622float2(*(__nv_bfloat162*)&v.w); dst[6] = f.x; dst[7] = f.y;
}

// ---------------- basis + decay ----------------------------------------------
__global__ void k_basis() {
    int m = blockIdx.x * 256 + threadIdx.x;
    if (m >= NMODE) return;
    int kx = m / NPAIR, r = m % NPAIR, ky = r / 9, kz = r % 9;
    float fx = kx * 0.0625f, fy = ky * 0.0625f, fz = kz * 0.0625f;
    float px[4] = {1.f, fx, fx * fx, fx * fx * fx};
    float py[4] = {1.f, fy, fy * fy, fy * fy * fy};
    float pz[4] = {1.f, fz, fz * fz, fz * fz * fz};
#pragma unroll
    for (int t = 0; t < 20; t++)
        g_bas[m * 20 + t] = px[c_tp[t]] * py[c_tq[t]] * pz[c_tr[t]];
    g_dec[m] = expf(-2.0f * (fx * fx + fy * fy + fz * fz));
}

// ---------------- Rk = decay/64^3 * P/(Q+eps), layout [m][i][o] (bf16) --------
__global__ void k_rk(const float* __restrict__ P, const float* __restrict__ Q) {
    __shared__ float sp[64 * 65];
    __shared__ float sq[64 * 65];
    __shared__ float sb[96 * 20];
    __shared__ float sd[96];
    int i = blockIdx.y;
    int m0 = blockIdx.x * 96;
    int o = threadIdx.x;  // 64 threads
    for (int idx = o; idx < 4096; idx += 64) {
        int oo = idx >> 6, c = idx & 63;
        sp[c * 65 + oo] = P[(size_t)oo * 4096 + i * 64 + c];
        sq[c * 65 + oo] = Q[(size_t)oo * 4096 + i * 64 + c];
    }
    for (int idx = o; idx < 96 * 20; idx += 64) sb[idx] = g_bas[m0 * 20 + idx];
    for (int idx = o; idx < 96; idx += 64) sd[idx] = g_dec[m0 + idx];
    __syncthreads();
    for (int mm = 0; mm < 96; mm++) {
        float pv = 0.f, qv = 0.f;
#pragma unroll
        for (int t = 0; t < 20; t++) {
            int di = c_tp[t] * 16 + c_tq[t] * 4 + c_tr[t];
            float bv = sb[mm * 20 + t];
            pv = fmaf(bv, sp[di * 65 + o], pv);
            qv = fmaf(bv, sq[di * 65 + o], qv);
        }
        float rr = sd[mm] * (1.0f / 262144.0f) * (pv / (qv + 1e-6f));
        g_Rk[((size_t)(m0 + mm) * 64 + i) * 64 + o] = __float2bfloat16_rn(rr);
    }
}

// ---------------- input projection (pencil) + z-DFT ----------------------------
__global__ void k_inproj(const float* __restrict__ x, const float* __restrict__ Wi,
                         const float* __restrict__ bi) {
    __shared__ float sh[64 * 68];
    __shared__ float sx[3 * 64];
    __shared__ float2 tw8[64];
    int t = threadIdx.x;  // 256
    int bx = blockIdx.x;  // b*4096 + p
    int b = bx >> 12, p = bx & 4095;
    if (t < 64) {
        int z0 = t >> 3, k = (t & 7) + 1;
        float s, c;
        sincosf(-TWO_PI * (float)(z0 * k) * (1.0f / 64.0f), &s, &c);
        tw8[t] = make_float2(c, s);
    }
    if (t >= 64 && t < 256) {
        int idx = t - 64;
        int c = idx >> 6, z = idx & 63;
        sx[idx] = x[((size_t)(b * 3 + c) << 18) + (size_t)p * 64 + z];
    }
    __syncthreads();
    {
        int w = t & 63, zq = t >> 6;
        float wc0 = Wi[w], wc1 = Wi[64 + w], wc2 = Wi[128 + w];
        float bv = bi[w];
#pragma unroll
        for (int z = zq * 16; z < zq * 16 + 16; z++) {
            float v = bv;
            v = fmaf(sx[z], wc0, v);
            v = fmaf(sx[64 + z], wc1, v);
            v = fmaf(sx[128 + z], wc2, v);
            sh[w * 68 + z] = v;
        }
    }
    __syncthreads();
    // write h tile (contiguous pencil-major layout)
    float* hbase = g_hA + (size_t)bx * 4096;
    for (int idx4 = t; idx4 < 1024; idx4 += 256) {
        int w = idx4 >> 4, z4 = (idx4 & 15) * 4;
        *(float4*)&hbase[idx4 * 4] = *(const float4*)&sh[w * 68 + z4];
    }
    if (t < 64) {
        float ar[9], ai[9];
        zdft_radix8(sh + t * 68, tw8, ar, ai);
        __nv_bfloat162* zo = g_Zf + (size_t)bx * 576 + t * 9;
#pragma unroll
        for (int k = 0; k < 9; k++) zo[k] = __floats2bfloat162_rn(ar[k], ai[k]);
    }
}

// ---------------- forward y-DFT from Zf(bf16) (radix-4), i-chunk of 4 ----------
__global__ void k_yfwd() {
    extern __shared__ float ds[];
    float* sZ = ds;          // [y][ii][18]
    float* sG = ds + 4608;
    __shared__ float2 tw[64];
    int t = threadIdx.x;  // 256
    if (t < 64) { float s, c; sincosf(TWO_PI * t * (1.0f / 64.0f), &s, &c); tw[t] = make_float2(c, s); }
    int bx = blockIdx.x;
    int ig = bx & 15, bxx = bx >> 4;
    int b = bxx >> 6, x = bxx & 63;
    const __nv_bfloat162* Zb = g_Zf + ((size_t)(b * 4096 + x * 64)) * 576 + ig * 36;
    for (int u = t; u < 576; u += 256) {
        int y = u / 9, j = u % 9;
        uint4 v = *(const uint4*)(Zb + (size_t)y * 576 + j * 4);
        bf8_to_f8(v, &sZ[y * 72 + j * 8]);
    }
    __syncthreads();
    for (int task = t; task < 576; task += 256) {
        int y0 = task / 36, rem = task % 36, ii = rem / 9, kz = rem % 9;
        int si = ii * 18 + kz * 2;
        float zr0 = sZ[y0 * 72 + si],        zi0 = sZ[y0 * 72 + si + 1];
        float zr1 = sZ[(16 + y0) * 72 + si], zi1 = sZ[(16 + y0) * 72 + si + 1];
        float zr2 = sZ[(32 + y0) * 72 + si], zi2 = sZ[(32 + y0) * 72 + si + 1];
        float zr3 = sZ[(48 + y0) * 72 + si], zi3 = sZ[(48 + y0) * 72 + si + 1];
        int gb = (y0 * 16 + ii) * 18 + kz * 2;
        sG[gb]       = zr0 + zr1 + zr2 + zr3;  sG[gb + 1]   = zi0 + zi1 + zi2 + zi3;
        sG[gb + 72]  = zr0 + zi1 - zr2 - zi3;  sG[gb + 73]  = zi0 - zr1 - zi2 + zr3;
        sG[gb + 144] = zr0 - zr1 + zr2 - zr3;  sG[gb + 145] = zi0 - zi1 + zi2 - zi3;
        sG[gb + 216] = zr0 - zi1 - zr2 + zi3;  sG[gb + 217] = zi0 + zr1 - zi2 - zr3;
    }
    __syncthreads();
    for (int oi = t; oi < 576; oi += 256) {
        int ii = oi / 144, rem = oi % 144, ky = rem / 9, kz = rem % 9;
        int r = ky & 3;
        const float* gp = sG + (r * 4 + ii) * 18 + kz * 2;
        float ar = 0.f, ai = 0.f;
#pragma unroll
        for (int y0 = 0; y0 < 16; y0++) {
            float2 w = tw[(ky * y0) & 63];
            float gr = gp[y0 * 288], gi = gp[y0 * 288 + 1];
            ar = fmaf(gr, w.x, fmaf(gi, w.y, ar));
            ai = fmaf(gi, w.x, fmaf(-gr, w.y, ai));
        }
        int i = ig * 4 + ii;
        size_t o = ((size_t)((b * 64 + i) * 64) + x) * 288 + rem * 2;
        g_Yf[o] = ar; g_Yf[o + 1] = ai;
    }
}

// ---------------- forward x-DFT: 64 -> 16 with radix-4 split (grid 512) --------
__global__ void k_xfwd() {
    __shared__ float sy[64 * 72];
    __shared__ float sG[16 * 288];
    __shared__ float2 tw[64];
    int t = threadIdx.x;  // 288
    if (t < 64) { float s, c; sincosf(TWO_PI * t * (1.0f / 64.0f), &s, &c); tw[t] = make_float2(c, s); }
    int bx = blockIdx.x;  // 512 = (b*64+i)*4 + pg
    int pg = bx & 3, bi = bx >> 2;
    size_t ybase = (size_t)bi * 64 * 288 + pg * 72;
    for (int idx = t; idx < 4608; idx += 288) {
        int x = idx / 72, r = idx % 72;
        sy[idx] = g_Yf[ybase + (size_t)x * 288 + r];
    }
    __syncthreads();
    for (int task = t; task < 576; task += 288) {
        int x0 = task / 36, pp = task % 36;
        float zr0 = sy[x0 * 72 + 2 * pp],        zi0 = sy[x0 * 72 + 2 * pp + 1];
        float zr1 = sy[(16 + x0) * 72 + 2 * pp], zi1 = sy[(16 + x0) * 72 + 2 * pp + 1];
        float zr2 = sy[(32 + x0) * 72 + 2 * pp], zi2 = sy[(32 + x0) * 72 + 2 * pp + 1];
        float zr3 = sy[(48 + x0) * 72 + 2 * pp], zi3 = sy[(48 + x0) * 72 + 2 * pp + 1];
        int gb = x0 * 288 + pp * 2;
        sG[gb]       = zr0 + zr1 + zr2 + zr3;  sG[gb + 1]   = zi0 + zi1 + zi2 + zi3;
        sG[gb + 72]  = zr0 + zi1 - zr2 - zi3;  sG[gb + 73]  = zi0 - zr1 - zi2 + zr3;
        sG[gb + 144] = zr0 - zr1 + zr2 - zr3;  sG[gb + 145] = zi0 - zi1 + zi2 - zi3;
        sG[gb + 216] = zr0 - zi1 - zr2 + zi3;  sG[gb + 217] = zi0 + zr1 - zi2 - zr3;
    }
    __syncthreads();
    int b = bi >> 6, i = bi & 63;
    for (int oi = t; oi < 576; oi += 288) {
        int kx = oi / 36, pp = oi % 36;
        int r = kx & 3;
        const float* gp = sG + r * 72 + 2 * pp;
        float ar = 0.f, ai = 0.f;
#pragma unroll
        for (int x0 = 0; x0 < 16; x0++) {
            float2 w = tw[(kx * x0) & 63];
            float gr = gp[x0 * 288], gi = gp[x0 * 288 + 1];
            ar = fmaf(gr, w.x, fmaf(gi, w.y, ar));
            ai = fmaf(gi, w.x, fmaf(-gr, w.y, ai));
        }
        int m = kx * 144 + pg * 36 + pp;
        size_t o = ((size_t)(b * NMODE + m) * 64 + i) * 2;
        g_Xm[o] = ar; g_Xm[o + 1] = ai;
    }
}

// ---------------- per-mode channel mix (4 modes / 256-thread block) ------------
__global__ void k_mix() {
    __shared__ float sx[4][4][64];
    int m0 = blockIdx.x * 4;
    int t = threadIdx.x;
    int mm = t >> 6, o = t & 63;
    for (int idx = t; idx < 1024; idx += 256) {
        int lm = idx >> 8, r = idx & 255;
        int b = r >> 7, rr = r & 127;
        sx[lm][b * 2 + (rr & 1)][rr >> 1] =
            g_Xm[((size_t)(b * NMODE + m0 + lm) * 64) * 2 + rr];
    }
    __syncthreads();
    float a0r = 0.f, a0i = 0.f, a1r = 0.f, a1i = 0.f;
    const __nv_bfloat16* rk = g_Rk + (size_t)(m0 + mm) * 4096 + o;
#pragma unroll 8
    for (int i = 0; i < 64; i++) {
        float r = __bfloat162float(rk[i * 64]);
        a0r = fmaf(sx[mm][0][i], r, a0r);
        a0i = fmaf(sx[mm][1][i], r, a0i);
        a1r = fmaf(sx[mm][2][i], r, a1r);
        a1i = fmaf(sx[mm][3][i], r, a1i);
    }
    int m = m0 + mm;
    size_t o0 = ((size_t)o * NMODE + m) * 2;
    size_t o1 = ((size_t)(64 + o) * NMODE + m) * 2;
    g_Om[o0] = a0r; g_Om[o0 + 1] = a0i;
    g_Om[o1] = a1r; g_Om[o1 + 1] = a1i;
}

// ---------------- fused inverse x + y: Om -> IY(bf16) --------------------------
__global__ void k_inv() {
    extern __shared__ float ds[];
    float* sOm = ds;
    float* sIX = ds + 4608;
    __shared__ float2 tw[64];
    int t = threadIdx.x;  // 256
    if (t < 64) { float s, c; sincosf(TWO_PI * t * (1.0f / 64.0f), &s, &c); tw[t] = make_float2(c, s); }
    int bx = blockIdx.x;
    int xq = bx & 3, bo = bx >> 2;
    int b = bo >> 6, o = bo & 63;
    size_t ob = (size_t)bo * 4608;
    for (int idx4 = t; idx4 < 1152; idx4 += 256)
        *(float4*)&sOm[idx4 * 4] = *(const float4*)&g_Om[ob + idx4 * 4];
    __syncthreads();
    for (int oi = t; oi < 2304; oi += 256) {
        int xl = oi / 144, pr = oi % 144;
        int x = xq * 16 + xl;
        float ar = 0.f, ai = 0.f;
#pragma unroll
        for (int kx = 0; kx < 16; kx++) {
            float2 w = tw[(kx * x) & 63];
            float vr = sOm[(kx * 144 + pr) * 2], vi = sOm[(kx * 144 + pr) * 2 + 1];
            ar = fmaf(vr, w.x, fmaf(-vi, w.y, ar));
            ai = fmaf(vr, w.y, fmaf(vi, w.x, ai));
        }
        sIX[xl * 288 + pr * 2] = ar;
        sIX[xl * 288 + pr * 2 + 1] = ai;
    }
    __syncthreads();
    for (int oi = t; oi < 9216; oi += 256) {
        int xl = oi / 576, rem = oi % 576, y = rem / 9, kz = rem % 9;
        const float* ip = sIX + xl * 288 + kz * 2;
        float ar = 0.f, ai = 0.f;
#pragma unroll
        for (int ky = 0; ky < 16; ky++) {
            float2 w = tw[(ky * y) & 63];
            float vr = ip[ky * 18], vi = ip[ky * 18 + 1];
            ar = fmaf(vr, w.x, fmaf(-vi, w.y, ar));
            ai = fmaf(vr, w.y, fmaf(vi, w.x, ai));
        }
        int p = (xq * 16 + xl) * 64 + y;
        g_IY[((size_t)(b * 4096 + p)) * 576 + o * 9 + kz] =
            __floats2bfloat162_rn(ar, ai);
    }
}

// ---------------- epilogue: irfft-z + 3xTF32 conv (A from gmem) + GELU + z-DFT -
// dyn smem: sh[4352] | shf[4352] | siy[1152] | tz[1024] | scb[64] = 43776 B
__global__ void __launch_bounds__(256, 4)
k_epilogue(int srcA, const float* __restrict__ cw,
           const float* __restrict__ cb, int doZf) {
    const float* __restrict__ hs = srcA ? g_hA : g_hB;
    float* __restrict__ hd = srcA ? g_hB : g_hA;
    extern __shared__ float dsm[];
    float* sh  = dsm;
    float* shf = dsm + 4352;
    float* siy = dsm + 8704;
    float2* tz = (float2*)(dsm + 9856);
    float* scb = dsm + 10880;
    int t = threadIdx.x;  // 256
    int bx = blockIdx.x;  // b*4096 + p
    size_t hb = (size_t)bx * 4096;

    // phase A: loads — h tile is one contiguous 16 KB block now
    for (int idx4 = t; idx4 < 1024; idx4 += 256) {
        int i = idx4 >> 4, z4 = (idx4 & 15) * 4;
        *(float4*)&sh[i * 68 + z4] = *(const float4*)&hs[hb + idx4 * 4];
    }
    {
        const uint4* iyb = (const uint4*)(g_IY + (size_t)bx * 576);
        for (int u = t; u < 144; u += 256)
            bf8_to_f8(iyb[u], &siy[u * 8]);
    }
    for (int idx = t; idx < 512; idx += 256) {
        int z = idx >> 3, k = (idx & 7) + 1;
        float s, c;
        sincosf(TWO_PI * (float)((z * k) & 63) * (1.0f / 64.0f), &s, &c);
        tz[idx] = make_float2(c, s);
    }
    if (t < 64) scb[t] = cb[t];
    __syncthreads();

    // pass 1: hf[o][z] via irfft over z (bins 0..8)
    {
        int o = t & 63, zq = t >> 6;
        float f0 = siy[o * 18];
        float fr[8], fi[8];
#pragma unroll
        for (int k = 0; k < 8; k++) {
            fr[k] = 2.0f * siy[o * 18 + 2 * (k + 1)];
            fi[k] = 2.0f * siy[o * 18 + 2 * (k + 1) + 1];
        }
        for (int z = zq * 16; z < zq * 16 + 16; z++) {
            float hf = f0;
#pragma unroll
            for (int k = 0; k < 8; k++) {
                float2 w = tz[z * 8 + k];
                hf = fmaf(fr[k], w.x, hf);
                hf = fmaf(-fi[k], w.y, hf);
            }
            shf[o * 68 + z] = hf;
        }
    }
    __syncthreads();

    // pass 2: 3xTF32 mma conv, A fragments loaded straight from gmem (L2-hot)
    int lane = t & 31;
    int w = t >> 5;
    int o0 = (w & 3) * 16;
    int zg = (w >> 2) * 32;
    int orow = lane >> 2, icol = lane & 3;
    float c[4][4];
    {
        float bv0 = scb[o0 + orow];
        float bv1 = scb[o0 + orow + 8];
#pragma unroll
        for (int nt = 0; nt < 4; nt++) {
            c[nt][0] = bv0; c[nt][1] = bv0;
            c[nt][2] = bv1; c[nt][3] = bv1;
        }
    }
#pragma unroll
    for (int k0 = 0; k0 < 64; k0 += 8) {
        float a0 = __ldg(&cw[(o0 + orow) * 64 + k0 + icol]);
        float a1 = __ldg(&cw[(o0 + orow + 8) * 64 + k0 + icol]);
        float a2 = __ldg(&cw[(o0 + orow) * 64 + k0 + icol + 4]);
        float a3 = __ldg(&cw[(o0 + orow + 8) * 64 + k0 + icol + 4]);
        uint32_t ah0 = f2tf(a0), ah1 = f2tf(a1), ah2 = f2tf(a2), ah3 = f2tf(a3);
        uint32_t al0 = f2tf(a0 - __uint_as_float(ah0));
        uint32_t al1 = f2tf(a1 - __uint_as_float(ah1));
        uint32_t al2 = f2tf(a2 - __uint_as_float(ah2));
        uint32_t al3 = f2tf(a3 - __uint_as_float(ah3));
#pragma unroll
        for (int nt = 0; nt < 4; nt++) {
            int z0 = zg + nt * 8;
            float b0 = sh[(k0 + icol) * 68 + z0 + orow];
            float b1 = sh[(k0 + icol + 4) * 68 + z0 + orow];
            uint32_t bh0 = f2tf(b0), bh1 = f2tf(b1);
            uint32_t bl0 = f2tf(b0 - __uint_as_float(bh0));
            uint32_t bl1 = f2tf(b1 - __uint_as_float(bh1));
            mma_tf32(c[nt], ah0, ah1, ah2, ah3, bl0, bl1);
            mma_tf32(c[nt], al0, al1, al2, al3, bh0, bh1);
            mma_tf32(c[nt], ah0, ah1, ah2, ah3, bh0, bh1);
        }
    }
    // fuse irfft term + residual + gelu; store contiguous; keep results
#pragma unroll
    for (int nt = 0; nt < 4; nt++) {
        int zc = zg + nt * 8 + 2 * icol;
        int r0 = o0 + orow, r1 = r0 + 8;
        float v00 = gelu_exact(c[nt][0] + shf[r0 * 68 + zc]     + sh[r0 * 68 + zc]);
        float v01 = gelu_exact(c[nt][1] + shf[r0 * 68 + zc + 1] + sh[r0 * 68 + zc + 1]);
        float v10 = gelu_exact(c[nt][2] + shf[r1 * 68 + zc]     + sh[r1 * 68 + zc]);
        float v11 = gelu_exact(c[nt][3] + shf[r1 * 68 + zc + 1] + sh[r1 * 68 + zc + 1]);
        *(float2*)&hd[hb + r0 * 64 + zc] = make_float2(v00, v01);
        *(float2*)&hd[hb + r1 * 64 + zc] = make_float2(v10, v11);
        c[nt][0] = v00; c[nt][1] = v01; c[nt][2] = v10; c[nt][3] = v11;
    }

    // phase 3: forward z-DFT of h_new (4-way partials into shf/siy overlay)
    if (doZf) {
        __syncthreads();
#pragma unroll
        for (int nt = 0; nt < 4; nt++) {
            int zc = zg + nt * 8 + 2 * icol;
            int r0 = o0 + orow, r1 = r0 + 8;
            sh[r0 * 68 + zc] = c[nt][0]; sh[r0 * 68 + zc + 1] = c[nt][1];
            sh[r1 * 68 + zc] = c[nt][2]; sh[r1 * 68 + zc + 1] = c[nt][3];
        }
        __syncthreads();
        {
            int row = t & 63, q = t >> 6;  // q handles z0 in {q, q+4}
            const float* rp = sh + row * 68;
            float ar[9], ai[9];
#pragma unroll
            for (int k = 0; k < 9; k++) { ar[k] = 0.f; ai[k] = 0.f; }
            const float S = 0.70710678118654752f;
#pragma unroll
            for (int j = 0; j < 2; j++) {
                int z0 = q + j * 4;
                float x0 = rp[z0], x1 = rp[z0 + 8], x2 = rp[z0 + 16], x3 = rp[z0 + 24];
                float x4 = rp[z0 + 32], x5 = rp[z0 + 40], x6 = rp[z0 + 48], x7 = rp[z0 + 56];
                float a0 = x0 + x4, A1 = x0 - x4;
                float a2 = x2 + x6, a3 = x2 - x6;
                float a4 = x1 + x5, a5 = x1 - x5;
                float a6 = x3 + x7, a7 = x3 - x7;
                float b0 = a0 + a2, b1 = a4 + a6;
                float F0  = b0 + b1, F4 = b0 - b1;
                float F2r = a0 - a2, F2i = -(a4 - a6);
                float u = S * (a5 - a7), v = S * (a5 + a7);
                float F1r = A1 + u, F1i = -(a3 + v);
                float F3r = A1 - u, F3i = a3 - v;
#pragma unroll
                for (int kk = 0; kk < 8; kk++) {
                    float2 W = tz[z0 * 8 + kk];
                    float wx = W.x, wy = -W.y;
                    float fr, fi;
                    if (kk == 0) { fr = F1r; fi = F1i; }
                    else if (kk == 1) { fr = F2r; fi = F2i; }
                    else if (kk == 2) { fr = F3r; fi = F3i; }
                    else if (kk == 3) { fr = F4;  fi = 0.f; }
                    else if (kk == 4) { fr = F3r; fi = -F3i; }
                    else if (kk == 5) { fr = F2r; fi = -F2i; }
                    else if (kk == 6) { fr = F1r; fi = -F1i; }
                    else { fr = F0; fi = 0.f; }
                    ar[kk + 1] = fmaf(fr, wx, fmaf(-fi, wy, ar[kk + 1]));
                    ai[kk + 1] = fmaf(fr, wy, fmaf(fi, wx, ai[kk + 1]));
                }
                ar[0] += F0;
            }
            float* sp = shf + (row * 4 + q) * 18;
#pragma unroll
            for (int k = 0; k < 9; k++) { sp[2 * k] = ar[k]; sp[2 * k + 1] = ai[k]; }
        }
        __syncthreads();
        if (t < 64) {
            __nv_bfloat162* zo = g_Zf + (size_t)bx * 576 + t * 9;
            const float* sp = shf + t * 72;
#pragma unroll
            for (int k = 0; k < 9; k++) {
                float re = sp[2 * k] + sp[18 + 2 * k] + sp[36 + 2 * k] + sp[54 + 2 * k];
                float im = sp[2 * k + 1] + sp[18 + 2 * k + 1] + sp[36 + 2 * k + 1] + sp[54 + 2 * k + 1];
                zo[k] = __floats2bfloat162_rn(re, im);
            }
        }
    }
}

// ---------------- output projection (pencil-major h) ---------------------------
// grid (1024, 2): block = 4 pencils, thread = (pl, z)
__global__ void k_outproj(const float* __restrict__ Wo, const float* __restrict__ bo,
                          float* __restrict__ out) {
    int t = threadIdx.x;
    int pl = t >> 6, z = t & 63;
    int b = blockIdx.y;
    int pen = blockIdx.x * 4 + pl;
    const float* hp = g_hA + ((size_t)(b * 4096 + pen)) * 4096 + z;
    float a0 = bo[0], a1 = bo[1], a2 = bo[2];
#pragma unroll 8
    for (int w = 0; w < 64; w++) {
        float v = hp[w * 64];
        a0 = fmaf(v, __ldg(&Wo[w * 3 + 0]), a0);
        a1 = fmaf(v, __ldg(&Wo[w * 3 + 1]), a1);
        a2 = fmaf(v, __ldg(&Wo[w * 3 + 2]), a2);
    }
    size_t pt = (size_t)pen * 64 + z;
    out[((size_t)(b * 3 + 0) << 18) + pt] = a0;
    out[((size_t)(b * 3 + 1) << 18) + pt] = a1;
    out[((size_t)(b * 3 + 2) << 18) + pt] = a2;
}

// ---------------- launch ---------------------------------------------------------
extern "C" void kernel_launch(void* const* d_in, const int* in_sizes, int n_in,
                              void* d_out, int out_size) {
    const float* x    = (const float*)d_in[0];
    const float* W_in = (const float*)d_in[1];
    const float* b_in = (const float*)d_in[2];
    const float* W_out= (const float*)d_in[3];
    const float* b_out= (const float*)d_in[4];
    const float* Pc   = (const float*)d_in[5];
    const float* Qc   = (const float*)d_in[6];
    const float* cw   = (const float*)d_in[7];
    const float* cb   = (const float*)d_in[8];
    float* out = (float*)d_out;

    const int epi_smem = 10944 * 4;  // 43776 bytes
    cudaFuncSetAttribute(k_epilogue, cudaFuncAttributeMaxDynamicSharedMemorySize, epi_smem);

    k_basis<<<9, 256>>>();
    k_inproj<<<8192, 256>>>(x, W_in, b_in);
    for (int l = 0; l < 4; l++) {
        int srcA = (l % 2 == 0) ? 1 : 0;
        k_rk<<<dim3(24, 64), 64>>>(Pc + (size_t)l * 262144, Qc + (size_t)l * 262144);
        k_yfwd<<<2048, 256, 36864>>>();
        k_xfwd<<<512, 288>>>();
        k_mix<<<576, 256>>>();
        k_inv<<<512, 256, 36864>>>();
        k_epilogue<<<8192, 256, epi_smem>>>(srcA, cw + (size_t)l * 4096,
                                            cb + (size_t)l * 64, l < 3 ? 1 : 0);
    }
    k_outproj<<<dim3(1024, 2), 256>>>(W_out, b_out, out);
}

// round 15
// speedup vs baseline: 1.0956x; 1.0956x over previous
#include <cuda_runtime.h>
#include <cuda_bf16.h>
#include <math.h>
#include <stdint.h>

#define NPT 262144
#define NMODE 2304
#define NPAIR 144
#define TWO_PI 6.283185307179586f

// ---------------- device-global scratch (no allocations allowed) -------------
__device__ float g_hA[2 * 64 * NPT];              // [b][i][p*64+z] (R12 layout)
__device__ float g_hB[2 * 64 * NPT];
__device__ __nv_bfloat162 g_Zf[2 * 4096 * 576];   // [b][p][i][kz]  (bf16 cplx)
__device__ float g_Yf[2 * 64 * 64 * 288];         // [b][i][x][(ky*9+kz)*2]
__device__ float g_Xm[2 * NMODE * 64 * 2];        // [b][m][i] complex
__device__ float g_Om[2 * 64 * NMODE * 2];        // [b][o][m] complex
__device__ __nv_bfloat162 g_IY[2 * 4096 * 576];   // [b][p][o][kz]  (bf16 cplx)
__device__ __nv_bfloat16 g_Rk[NMODE * 64 * 64];   // [m][i][o]  (bf16)
__device__ float g_bas[NMODE * 20];
__device__ float g_dec[NMODE];
__device__ float2 g_tw64[64];                     // e^{+2pi i u/64}
__device__ float2 g_tz[512];                      // [z][k-1] e^{+2pi i z k/64}

// 20 polynomial terms (p,q,r) with p+q+r < 4
__device__ __constant__ int c_tp[20] = {0,0,0,0,0,0,0,0,0,0, 1,1,1,1,1,1, 2,2,2, 3};
__device__ __constant__ int c_tq[20] = {0,0,0,0,1,1,1,2,2,3, 0,0,0,1,1,2, 0,0,1, 0};
__device__ __constant__ int c_tr[20] = {0,1,2,3,0,1,2,0,1,0, 0,1,2,0,1,0, 0,1,0, 0};

__device__ __forceinline__ float gelu_exact(float v) {
    return 0.5f * v * (1.0f + erff(v * 0.70710678118654752f));
}

__device__ __forceinline__ uint32_t f2tf(float x) {
    uint32_t r;
    asm("cvt.rna.tf32.f32 %0, %1;" : "=r"(r) : "f"(x));
    return r;
}

__device__ __forceinline__ void mma_tf32(float* c, uint32_t a0, uint32_t a1,
                                         uint32_t a2, uint32_t a3,
                                         uint32_t b0, uint32_t b1) {
    asm volatile(
        "mma.sync.aligned.m16n8k8.row.col.f32.tf32.tf32.f32 "
        "{%0,%1,%2,%3}, {%4,%5,%6,%7}, {%8,%9}, {%0,%1,%2,%3};\n"
        : "+f"(c[0]), "+f"(c[1]), "+f"(c[2]), "+f"(c[3])
        : "r"(a0), "r"(a1), "r"(a2), "r"(a3), "r"(b0), "r"(b1));
}

// radix-8 real z-DFT over 64 elements -> 9 cplx. tw[z0*8+(k-1)] = e^{-2pi i z0 k/64}
__device__ __forceinline__ void zdft_radix8(const float* row, const float2* tw,
                                            float* ar, float* ai) {
#pragma unroll
    for (int k = 0; k < 9; k++) { ar[k] = 0.f; ai[k] = 0.f; }
    const float S = 0.70710678118654752f;
#pragma unroll
    for (int z0 = 0; z0 < 8; z0++) {
        float x0 = row[z0], x1 = row[z0 + 8], x2 = row[z0 + 16], x3 = row[z0 + 24];
        float x4 = row[z0 + 32], x5 = row[z0 + 40], x6 = row[z0 + 48], x7 = row[z0 + 56];
        float a0 = x0 + x4, A1 = x0 - x4;
        float a2 = x2 + x6, a3 = x2 - x6;
        float a4 = x1 + x5, a5 = x1 - x5;
        float a6 = x3 + x7, a7 = x3 - x7;
        float b0 = a0 + a2, b1 = a4 + a6;
        float F0  = b0 + b1, F4 = b0 - b1;
        float F2r = a0 - a2, F2i = -(a4 - a6);
        float u = S * (a5 - a7), v = S * (a5 + a7);
        float F1r = A1 + u, F1i = -(a3 + v);
        float F3r = A1 - u, F3i = a3 - v;
        const float2* w = tw + z0 * 8;
        ar[0] += F0;
        { float2 W = w[0]; ar[1] = fmaf(F1r, W.x, fmaf(-F1i, W.y, ar[1])); ai[1] = fmaf(F1r, W.y, fmaf(F1i, W.x, ai[1])); }
        { float2 W = w[1]; ar[2] = fmaf(F2r, W.x, fmaf(-F2i, W.y, ar[2])); ai[2] = fmaf(F2r, W.y, fmaf(F2i, W.x, ai[2])); }
        { float2 W = w[2]; ar[3] = fmaf(F3r, W.x, fmaf(-F3i, W.y, ar[3])); ai[3] = fmaf(F3r, W.y, fmaf(F3i, W.x, ai[3])); }
        { float2 W = w[3]; ar[4] = fmaf(F4,  W.x, ar[4]); ai[4] = fmaf(F4, W.y, ai[4]); }
        { float2 W = w[4]; ar[5] = fmaf(F3r, W.x, fmaf( F3i, W.y, ar[5])); ai[5] = fmaf(F3r, W.y, fmaf(-F3i, W.x, ai[5])); }
        { float2 W = w[5]; ar[6] = fmaf(F2r, W.x, fmaf( F2i, W.y, ar[6])); ai[6] = fmaf(F2r, W.y, fmaf(-F2i, W.x, ai[6])); }
        { float2 W = w[6]; ar[7] = fmaf(F1r, W.x, fmaf( F1i, W.y, ar[7])); ai[7] = fmaf(F1r, W.y, fmaf(-F1i, W.x, ai[7])); }
        { float2 W = w[7]; ar[8] = fmaf(F0,  W.x, ar[8]); ai[8] = fmaf(F0, W.y, ai[8]); }
    }
}

// expand uint4 (8 bf16) into 8 floats at dst
__device__ __forceinline__ void bf8_to_f8(uint4 v, float* dst) {
    float2 f;
    f = __bfloat1622float2(*(__nv_bfloat162*)&v.x); dst[0] = f.x; dst[1] = f.y;
    f = __bfloat1622float2(*(__nv_bfloat162*)&v.y); dst[2] = f.x; dst[3] = f.y;
    f = __bfloat1622float2(*(__nv_bfloat162*)&v.z); dst[4] = f.x; dst[5] = f.y;
    f = __bfloat1622float2(*(__nv_bfloat162*)&v.w); dst[6] = f.x; dst[7] = f.y;
}

// ---------------- basis + decay + twiddle tables -------------------------------
__global__ void k_basis() {
    int m = blockIdx.x * 256 + threadIdx.x;
    if (m < 64) {
        float s, c;
        sincosf(TWO_PI * (float)m * (1.0f / 64.0f), &s, &c);
        g_tw64[m] = make_float2(c, s);
    }
    if (m < 512) {
        int z = m >> 3, k = (m & 7) + 1;
        float s, c;
        sincosf(TWO_PI * (float)((z * k) & 63) * (1.0f / 64.0f), &s, &c);
        g_tz[m] = make_float2(c, s);
    }
    if (m >= NMODE) return;
    int kx = m / NPAIR, r = m % NPAIR, ky = r / 9, kz = r % 9;
    float fx = kx * 0.0625f, fy = ky * 0.0625f, fz = kz * 0.0625f;
    float px[4] = {1.f, fx, fx * fx, fx * fx * fx};
    float py[4] = {1.f, fy, fy * fy, fy * fy * fy};
    float pz[4] = {1.f, fz, fz * fz, fz * fz * fz};
#pragma unroll
    for (int t = 0; t < 20; t++)
        g_bas[m * 20 + t] = px[c_tp[t]] * py[c_tq[t]] * pz[c_tr[t]];
    g_dec[m] = expf(-2.0f * (fx * fx + fy * fy + fz * fz));
}

// ---------------- input projection (pencil) + z-DFT ----------------------------
__global__ void k_inproj(const float* __restrict__ x, const float* __restrict__ Wi,
                         const float* __restrict__ bi) {
    __shared__ float sh[64 * 68];
    __shared__ float sx[3 * 64];
    __shared__ float2 tw8[64];
    int t = threadIdx.x;  // 256
    int bx = blockIdx.x;  // b*4096 + p
    int b = bx >> 12, p = bx & 4095;
    if (t < 64) {
        float2 v = g_tz[t];
        tw8[t] = make_float2(v.x, -v.y);  // e^{-2pi i z0 k/64}
    }
    if (t >= 64 && t < 256) {
        int idx = t - 64;
        int c = idx >> 6, z = idx & 63;
        sx[idx] = x[((size_t)(b * 3 + c) << 18) + (size_t)p * 64 + z];
    }
    __syncthreads();
    {
        int w = t & 63, zq = t >> 6;
        float wc0 = Wi[w], wc1 = Wi[64 + w], wc2 = Wi[128 + w];
        float bv = bi[w];
#pragma unroll
        for (int z = zq * 16; z < zq * 16 + 16; z++) {
            float v = bv;
            v = fmaf(sx[z], wc0, v);
            v = fmaf(sx[64 + z], wc1, v);
            v = fmaf(sx[128 + z], wc2, v);
            sh[w * 68 + z] = v;
        }
    }
    __syncthreads();
    size_t pb = (size_t)p * 64;
    for (int idx4 = t; idx4 < 1024; idx4 += 256) {
        int w = idx4 >> 4, z4 = (idx4 & 15) * 4;
        *(float4*)&g_hA[((size_t)(b * 64 + w) << 18) + pb + z4] =
            *(const float4*)&sh[w * 68 + z4];
    }
    if (t < 64) {
        float ar[9], ai[9];
        zdft_radix8(sh + t * 68, tw8, ar, ai);
        __nv_bfloat162* zo = g_Zf + (size_t)bx * 576 + t * 9;
#pragma unroll
        for (int k = 0; k < 9; k++) zo[k] = __floats2bfloat162_rn(ar[k], ai[k]);
    }
}

// ---------------- MERGED: forward y-DFT (blocks<2048) + Rk build (rest) --------
// dyn smem 41472 B. yfwd path: sZ[4608]|sG[4608]. rk path: sp|sq|sb|sd.
__global__ void k_yfwd_rk(const float* __restrict__ P, const float* __restrict__ Q) {
    extern __shared__ float ds[];
    __shared__ float2 tw[64];
    int t = threadIdx.x;  // 256
    int bx = blockIdx.x;

    if (bx < 2048) {
        // ---- yfwd ----
        float* sZ = ds;
        float* sG = ds + 4608;
        if (t < 64) tw[t] = g_tw64[t];
        int ig = bx & 15, bxx = bx >> 4;
        int b = bxx >> 6, x = bxx & 63;
        const __nv_bfloat162* Zb = g_Zf + ((size_t)(b * 4096 + x * 64)) * 576 + ig * 36;
        for (int u = t; u < 576; u += 256) {
            int y = u / 9, j = u % 9;
            uint4 v = *(const uint4*)(Zb + (size_t)y * 576 + j * 4);
            bf8_to_f8(v, &sZ[y * 72 + j * 8]);
        }
        __syncthreads();
        for (int task = t; task < 576; task += 256) {
            int y0 = task / 36, rem = task % 36, ii = rem / 9, kz = rem % 9;
            int si = ii * 18 + kz * 2;
            float zr0 = sZ[y0 * 72 + si],        zi0 = sZ[y0 * 72 + si + 1];
            float zr1 = sZ[(16 + y0) * 72 + si], zi1 = sZ[(16 + y0) * 72 + si + 1];
            float zr2 = sZ[(32 + y0) * 72 + si], zi2 = sZ[(32 + y0) * 72 + si + 1];
            float zr3 = sZ[(48 + y0) * 72 + si], zi3 = sZ[(48 + y0) * 72 + si + 1];
            int gb = (y0 * 16 + ii) * 18 + kz * 2;
            sG[gb]       = zr0 + zr1 + zr2 + zr3;  sG[gb + 1]   = zi0 + zi1 + zi2 + zi3;
            sG[gb + 72]  = zr0 + zi1 - zr2 - zi3;  sG[gb + 73]  = zi0 - zr1 - zi2 + zr3;
            sG[gb + 144] = zr0 - zr1 + zr2 - zr3;  sG[gb + 145] = zi0 - zi1 + zi2 - zi3;
            sG[gb + 216] = zr0 - zi1 - zr2 + zi3;  sG[gb + 217] = zi0 + zr1 - zi2 - zr3;
        }
        __syncthreads();
        for (int oi = t; oi < 576; oi += 256) {
            int ii = oi / 144, rem = oi % 144, ky = rem / 9, kz = rem % 9;
            int r = ky & 3;
            const float* gp = sG + (r * 4 + ii) * 18 + kz * 2;
            float ar = 0.f, ai = 0.f;
#pragma unroll
            for (int y0 = 0; y0 < 16; y0++) {
                float2 w = tw[(ky * y0) & 63];
                float gr = gp[y0 * 288], gi = gp[y0 * 288 + 1];
                ar = fmaf(gr, w.x, fmaf(gi, w.y, ar));
                ai = fmaf(gi, w.x, fmaf(-gr, w.y, ai));
            }
            int i = ig * 4 + ii;
            size_t o = ((size_t)((b * 64 + i) * 64) + x) * 288 + rem * 2;
            g_Yf[o] = ar; g_Yf[o + 1] = ai;
        }
    } else {
        // ---- rk: one i per block, 4 mode-groups of 24 across threads ----
        float* sp = ds;            // 4160
        float* sq = ds + 4160;     // 4160
        float* sb = ds + 8320;     // 1920
        float* sd = ds + 10240;    // 96
        int rb = bx - 2048;        // 1536 = i*24? no: rb = mchunk*64? use rb&63=i
        int i = rb & 63, m0 = (rb >> 6) * 96;
        for (int idx = t; idx < 4096; idx += 256) {
            int oo = idx >> 6, c = idx & 63;
            sp[c * 65 + oo] = P[(size_t)oo * 4096 + i * 64 + c];
            sq[c * 65 + oo] = Q[(size_t)oo * 4096 + i * 64 + c];
        }
        for (int idx = t; idx < 1920; idx += 256) sb[idx] = g_bas[m0 * 20 + idx];
        if (t < 96) sd[t] = g_dec[m0 + t];
        __syncthreads();
        int g = t >> 6, o = t & 63;
        for (int mm = g * 24; mm < g * 24 + 24; mm++) {
            float pv = 0.f, qv = 0.f;
#pragma unroll
            for (int tt = 0; tt < 20; tt++) {
                int di = c_tp[tt] * 16 + c_tq[tt] * 4 + c_tr[tt];
                float bv = sb[mm * 20 + tt];
                pv = fmaf(bv, sp[di * 65 + o], pv);
                qv = fmaf(bv, sq[di * 65 + o], qv);
            }
            float rr = sd[mm] * (1.0f / 262144.0f) * (pv / (qv + 1e-6f));
            g_Rk[((size_t)(m0 + mm) * 64 + i) * 64 + o] = __float2bfloat16_rn(rr);
        }
    }
}

// ---------------- forward x-DFT: 64 -> 16 with radix-4 split (grid 512) --------
__global__ void k_xfwd() {
    __shared__ float sy[64 * 72];
    __shared__ float sG[16 * 288];
    __shared__ float2 tw[64];
    int t = threadIdx.x;  // 288
    if (t < 64) tw[t] = g_tw64[t];
    int bx = blockIdx.x;  // 512 = (b*64+i)*4 + pg
    int pg = bx & 3, bi = bx >> 2;
    size_t ybase = (size_t)bi * 64 * 288 + pg * 72;
    for (int idx = t; idx < 4608; idx += 288) {
        int x = idx / 72, r = idx % 72;
        sy[idx] = g_Yf[ybase + (size_t)x * 288 + r];
    }
    __syncthreads();
    for (int task = t; task < 576; task += 288) {
        int x0 = task / 36, pp = task % 36;
        float zr0 = sy[x0 * 72 + 2 * pp],        zi0 = sy[x0 * 72 + 2 * pp + 1];
        float zr1 = sy[(16 + x0) * 72 + 2 * pp], zi1 = sy[(16 + x0) * 72 + 2 * pp + 1];
        float zr2 = sy[(32 + x0) * 72 + 2 * pp], zi2 = sy[(32 + x0) * 72 + 2 * pp + 1];
        float zr3 = sy[(48 + x0) * 72 + 2 * pp], zi3 = sy[(48 + x0) * 72 + 2 * pp + 1];
        int gb = x0 * 288 + pp * 2;
        sG[gb]       = zr0 + zr1 + zr2 + zr3;  sG[gb + 1]   = zi0 + zi1 + zi2 + zi3;
        sG[gb + 72]  = zr0 + zi1 - zr2 - zi3;  sG[gb + 73]  = zi0 - zr1 - zi2 + zr3;
        sG[gb + 144] = zr0 - zr1 + zr2 - zr3;  sG[gb + 145] = zi0 - zi1 + zi2 - zi3;
        sG[gb + 216] = zr0 - zi1 - zr2 + zi3;  sG[gb + 217] = zi0 + zr1 - zi2 - zr3;
    }
    __syncthreads();
    int b = bi >> 6, i = bi & 63;
    for (int oi = t; oi < 576; oi += 288) {
        int kx = oi / 36, pp = oi % 36;
        int r = kx & 3;
        const float* gp = sG + r * 72 + 2 * pp;
        float ar = 0.f, ai = 0.f;
#pragma unroll
        for (int x0 = 0; x0 < 16; x0++) {
            float2 w = tw[(kx * x0) & 63];
            float gr = gp[x0 * 288], gi = gp[x0 * 288 + 1];
            ar = fmaf(gr, w.x, fmaf(gi, w.y, ar));
            ai = fmaf(gi, w.x, fmaf(-gr, w.y, ai));
        }
        int m = kx * 144 + pg * 36 + pp;
        size_t o = ((size_t)(b * NMODE + m) * 64 + i) * 2;
        g_Xm[o] = ar; g_Xm[o + 1] = ai;
    }
}

// ---------------- per-mode channel mix (4 modes / 256-thread block) ------------
__global__ void k_mix() {
    __shared__ float sx[4][4][64];
    int m0 = blockIdx.x * 4;
    int t = threadIdx.x;
    int mm = t >> 6, o = t & 63;
    for (int idx = t; idx < 1024; idx += 256) {
        int lm = idx >> 8, r = idx & 255;
        int b = r >> 7, rr = r & 127;
        sx[lm][b * 2 + (rr & 1)][rr >> 1] =
            g_Xm[((size_t)(b * NMODE + m0 + lm) * 64) * 2 + rr];
    }
    __syncthreads();
    float a0r = 0.f, a0i = 0.f, a1r = 0.f, a1i = 0.f;
    const __nv_bfloat16* rk = g_Rk + (size_t)(m0 + mm) * 4096 + o;
#pragma unroll 8
    for (int i = 0; i < 64; i++) {
        float r = __bfloat162float(rk[i * 64]);
        a0r = fmaf(sx[mm][0][i], r, a0r);
        a0i = fmaf(sx[mm][1][i], r, a0i);
        a1r = fmaf(sx[mm][2][i], r, a1r);
        a1i = fmaf(sx[mm][3][i], r, a1i);
    }
    int m = m0 + mm;
    size_t o0 = ((size_t)o * NMODE + m) * 2;
    size_t o1 = ((size_t)(64 + o) * NMODE + m) * 2;
    g_Om[o0] = a0r; g_Om[o0 + 1] = a0i;
    g_Om[o1] = a1r; g_Om[o1 + 1] = a1i;
}

// ---------------- fused inverse x + y: Om -> IY(bf16) --------------------------
__global__ void k_inv() {
    extern __shared__ float ds[];
    float* sOm = ds;
    float* sIX = ds + 4608;
    __shared__ float2 tw[64];
    int t = threadIdx.x;  // 256
    if (t < 64) tw[t] = g_tw64[t];
    int bx = blockIdx.x;
    int xq = bx & 3, bo = bx >> 2;
    int b = bo >> 6, o = bo & 63;
    size_t ob = (size_t)bo * 4608;
    for (int idx4 = t; idx4 < 1152; idx4 += 256)
        *(float4*)&sOm[idx4 * 4] = *(const float4*)&g_Om[ob + idx4 * 4];
    __syncthreads();
    for (int oi = t; oi < 2304; oi += 256) {
        int xl = oi / 144, pr = oi % 144;
        int x = xq * 16 + xl;
        float ar = 0.f, ai = 0.f;
#pragma unroll
        for (int kx = 0; kx < 16; kx++) {
            float2 w = tw[(kx * x) & 63];
            float vr = sOm[(kx * 144 + pr) * 2], vi = sOm[(kx * 144 + pr) * 2 + 1];
            ar = fmaf(vr, w.x, fmaf(-vi, w.y, ar));
            ai = fmaf(vr, w.y, fmaf(vi, w.x, ai));
        }
        sIX[xl * 288 + pr * 2] = ar;
        sIX[xl * 288 + pr * 2 + 1] = ai;
    }
    __syncthreads();
    for (int oi = t; oi < 9216; oi += 256) {
        int xl = oi / 576, rem = oi % 576, y = rem / 9, kz = rem % 9;
        const float* ip = sIX + xl * 288 + kz * 2;
        float ar = 0.f, ai = 0.f;
#pragma unroll
        for (int ky = 0; ky < 16; ky++) {
            float2 w = tw[(ky * y) & 63];
            float vr = ip[ky * 18], vi = ip[ky * 18 + 1];
            ar = fmaf(vr, w.x, fmaf(-vi, w.y, ar));
            ai = fmaf(vr, w.y, fmaf(vi, w.x, ai));
        }
        int p = (xq * 16 + xl) * 64 + y;
        g_IY[((size_t)(b * 4096 + p)) * 576 + o * 9 + kz] =
            __floats2bfloat162_rn(ar, ai);
    }
}

// ---------------- epilogue: irfft-z + 3xTF32 conv (A from gmem) + GELU + z-DFT -
// dyn smem: sh[4352] | shf[4352] | siy[1152] | tz[1024] | scb[64] = 43776 B
__global__ void __launch_bounds__(256, 4)
k_epilogue(int srcA, const float* __restrict__ cw,
           const float* __restrict__ cb, int doZf) {
    const float* __restrict__ hs = srcA ? g_hA : g_hB;
    float* __restrict__ hd = srcA ? g_hB : g_hA;
    extern __shared__ float dsm[];
    float* sh  = dsm;
    float* shf = dsm + 4352;
    float* siy = dsm + 8704;
    float2* tz = (float2*)(dsm + 9856);
    float* scb = dsm + 10880;
    int t = threadIdx.x;  // 256
    int bx = blockIdx.x;  // b*4096 + p
    int b = bx >> 12;
    int p = bx & 4095;
    size_t pbase = (size_t)p * 64;

    // phase A: loads (h, IY pencil(bf16), tz table, bias)
    for (int idx4 = t; idx4 < 1024; idx4 += 256) {
        int i = idx4 >> 4, z4 = (idx4 & 15) * 4;
        *(float4*)&sh[i * 68 + z4] =
            *(const float4*)&hs[((size_t)(b * 64 + i) << 18) + pbase + z4];
    }
    {
        const uint4* iyb = (const uint4*)(g_IY + (size_t)bx * 576);
        for (int u = t; u < 144; u += 256)
            bf8_to_f8(iyb[u], &siy[u * 8]);
    }
    {
        const float4* tzg = (const float4*)g_tz;
        float4* tzs = (float4*)tz;
        if (t < 256) tzs[t] = tzg[t];
    }
    if (t < 64) scb[t] = cb[t];
    __syncthreads();

    // pass 1: hf[o][z] via irfft over z (bins 0..8)
    {
        int o = t & 63, zq = t >> 6;
        float f0 = siy[o * 18];
        float fr[8], fi[8];
#pragma unroll
        for (int k = 0; k < 8; k++) {
            fr[k] = 2.0f * siy[o * 18 + 2 * (k + 1)];
            fi[k] = 2.0f * siy[o * 18 + 2 * (k + 1) + 1];
        }
        for (int z = zq * 16; z < zq * 16 + 16; z++) {
            float hf = f0;
#pragma unroll
            for (int k = 0; k < 8; k++) {
                float2 w = tz[z * 8 + k];
                hf = fmaf(fr[k], w.x, hf);
                hf = fmaf(-fi[k], w.y, hf);
            }
            shf[o * 68 + z] = hf;
        }
    }
    __syncthreads();

    // pass 2: 3xTF32 mma conv, A fragments loaded straight from gmem (L2-hot)
    int lane = t & 31;
    int w = t >> 5;
    int o0 = (w & 3) * 16;
    int zg = (w >> 2) * 32;
    int orow = lane >> 2, icol = lane & 3;
    float c[4][4];
    {
        float bv0 = scb[o0 + orow];
        float bv1 = scb[o0 + orow + 8];
#pragma unroll
        for (int nt = 0; nt < 4; nt++) {
            c[nt][0] = bv0; c[nt][1] = bv0;
            c[nt][2] = bv1; c[nt][3] = bv1;
        }
    }
#pragma unroll
    for (int k0 = 0; k0 < 64; k0 += 8) {
        float a0 = __ldg(&cw[(o0 + orow) * 64 + k0 + icol]);
        float a1 = __ldg(&cw[(o0 + orow + 8) * 64 + k0 + icol]);
        float a2 = __ldg(&cw[(o0 + orow) * 64 + k0 + icol + 4]);
        float a3 = __ldg(&cw[(o0 + orow + 8) * 64 + k0 + icol + 4]);
        uint32_t ah0 = f2tf(a0), ah1 = f2tf(a1), ah2 = f2tf(a2), ah3 = f2tf(a3);
        uint32_t al0 = f2tf(a0 - __uint_as_float(ah0));
        uint32_t al1 = f2tf(a1 - __uint_as_float(ah1));
        uint32_t al2 = f2tf(a2 - __uint_as_float(ah2));
        uint32_t al3 = f2tf(a3 - __uint_as_float(ah3));
#pragma unroll
        for (int nt = 0; nt < 4; nt++) {
            int z0 = zg + nt * 8;
            float b0 = sh[(k0 + icol) * 68 + z0 + orow];
            float b1 = sh[(k0 + icol + 4) * 68 + z0 + orow];
            uint32_t bh0 = f2tf(b0), bh1 = f2tf(b1);
            uint32_t bl0 = f2tf(b0 - __uint_as_float(bh0));
            uint32_t bl1 = f2tf(b1 - __uint_as_float(bh1));
            mma_tf32(c[nt], ah0, ah1, ah2, ah3, bl0, bl1);
            mma_tf32(c[nt], al0, al1, al2, al3, bh0, bh1);
            mma_tf32(c[nt], ah0, ah1, ah2, ah3, bh0, bh1);
        }
    }
    // fuse irfft term + residual + gelu; store; keep results
#pragma unroll
    for (int nt = 0; nt < 4; nt++) {
        int zc = zg + nt * 8 + 2 * icol;
        int r0 = o0 + orow, r1 = r0 + 8;
        float v00 = gelu_exact(c[nt][0] + shf[r0 * 68 + zc]     + sh[r0 * 68 + zc]);
        float v01 = gelu_exact(c[nt][1] + shf[r0 * 68 + zc + 1] + sh[r0 * 68 + zc + 1]);
        float v10 = gelu_exact(c[nt][2] + shf[r1 * 68 + zc]     + sh[r1 * 68 + zc]);
        float v11 = gelu_exact(c[nt][3] + shf[r1 * 68 + zc + 1] + sh[r1 * 68 + zc + 1]);
        *(float2*)&hd[((size_t)(b * 64 + r0) << 18) + pbase + zc] = make_float2(v00, v01);
        *(float2*)&hd[((size_t)(b * 64 + r1) << 18) + pbase + zc] = make_float2(v10, v11);
        c[nt][0] = v00; c[nt][1] = v01; c[nt][2] = v10; c[nt][3] = v11;
    }

    // phase 3: forward z-DFT of h_new (4-way partials into shf overlay)
    if (doZf) {
        __syncthreads();
#pragma unroll
        for (int nt = 0; nt < 4; nt++) {
            int zc = zg + nt * 8 + 2 * icol;
            int r0 = o0 + orow, r1 = r0 + 8;
            sh[r0 * 68 + zc] = c[nt][0]; sh[r0 * 68 + zc + 1] = c[nt][1];
            sh[r1 * 68 + zc] = c[nt][2]; sh[r1 * 68 + zc + 1] = c[nt][3];
        }
        __syncthreads();
        {
            int row = t & 63, q = t >> 6;  // q handles z0 in {q, q+4}
            const float* rp = sh + row * 68;
            float ar[9], ai[9];
#pragma unroll
            for (int k = 0; k < 9; k++) { ar[k] = 0.f; ai[k] = 0.f; }
            const float S = 0.70710678118654752f;
#pragma unroll
            for (int j = 0; j < 2; j++) {
                int z0 = q + j * 4;
                float x0 = rp[z0], x1 = rp[z0 + 8], x2 = rp[z0 + 16], x3 = rp[z0 + 24];
                float x4 = rp[z0 + 32], x5 = rp[z0 + 40], x6 = rp[z0 + 48], x7 = rp[z0 + 56];
                float a0 = x0 + x4, A1 = x0 - x4;
                float a2 = x2 + x6, a3 = x2 - x6;
                float a4 = x1 + x5, a5 = x1 - x5;
                float a6 = x3 + x7, a7 = x3 - x7;
                float b0 = a0 + a2, b1 = a4 + a6;
                float F0  = b0 + b1, F4 = b0 - b1;
                float F2r = a0 - a2, F2i = -(a4 - a6);
                float u = S * (a5 - a7), v = S * (a5 + a7);
                float F1r = A1 + u, F1i = -(a3 + v);
                float F3r = A1 - u, F3i = a3 - v;
#pragma unroll
                for (int kk = 0; kk < 8; kk++) {
                    float2 W = tz[z0 * 8 + kk];
                    float wx = W.x, wy = -W.y;
                    float fr, fi;
                    if (kk == 0) { fr = F1r; fi = F1i; }
                    else if (kk == 1) { fr = F2r; fi = F2i; }
                    else if (kk == 2) { fr = F3r; fi = F3i; }
                    else if (kk == 3) { fr = F4;  fi = 0.f; }
                    else if (kk == 4) { fr = F3r; fi = -F3i; }
                    else if (kk == 5) { fr = F2r; fi = -F2i; }
                    else if (kk == 6) { fr = F1r; fi = -F1i; }
                    else { fr = F0; fi = 0.f; }
                    ar[kk + 1] = fmaf(fr, wx, fmaf(-fi, wy, ar[kk + 1]));
                    ai[kk + 1] = fmaf(fr, wy, fmaf(fi, wx, ai[kk + 1]));
                }
                ar[0] += F0;
            }
            float* sp = shf + (row * 4 + q) * 18;
#pragma unroll
            for (int k = 0; k < 9; k++) { sp[2 * k] = ar[k]; sp[2 * k + 1] = ai[k]; }
        }
        __syncthreads();
        if (t < 64) {
            __nv_bfloat162* zo = g_Zf + (size_t)bx * 576 + t * 9;
            const float* sp = shf + t * 72;
#pragma unroll
            for (int k = 0; k < 9; k++) {
                float re = sp[2 * k] + sp[18 + 2 * k] + sp[36 + 2 * k] + sp[54 + 2 * k];
                float im = sp[2 * k + 1] + sp[18 + 2 * k + 1] + sp[36 + 2 * k + 1] + sp[54 + 2 * k + 1];
                zo[k] = __floats2bfloat162_rn(re, im);
            }
        }
    }
}

// ---------------- output projection --------------------------------------------
__global__ void k_outproj(const float* __restrict__ Wo, const float* __restrict__ bo,
                          float* __restrict__ out) {
    int p = blockIdx.x * 256 + threadIdx.x;
    int b = blockIdx.y;
    float a0 = bo[0], a1 = bo[1], a2 = bo[2];
    const float* hp = g_hA + ((size_t)b << 24) + p;
#pragma unroll 8
    for (int w = 0; w < 64; w++) {
        float v = hp[(size_t)w << 18];
        a0 = fmaf(v, __ldg(&Wo[w * 3 + 0]), a0);
        a1 = fmaf(v, __ldg(&Wo[w * 3 + 1]), a1);
        a2 = fmaf(v, __ldg(&Wo[w * 3 + 2]), a2);
    }
    out[((size_t)(b * 3 + 0) << 18) + p] = a0;
    out[((size_t)(b * 3 + 1) << 18) + p] = a1;
    out[((size_t)(b * 3 + 2) << 18) + p] = a2;
}

// ---------------- launch ---------------------------------------------------------
extern "C" void kernel_launch(void* const* d_in, const int* in_sizes, int n_in,
                              void* d_out, int out_size) {
    const float* x    = (const float*)d_in[0];
    const float* W_in = (const float*)d_in[1];
    const float* b_in = (const float*)d_in[2];
    const float* W_out= (const float*)d_in[3];
    const float* b_out= (const float*)d_in[4];
    const float* Pc   = (const float*)d_in[5];
    const float* Qc   = (const float*)d_in[6];
    const float* cw   = (const float*)d_in[7];
    const float* cb   = (const float*)d_in[8];
    float* out = (float*)d_out;

    const int epi_smem = 10944 * 4;   // 43776 bytes
    const int yr_smem  = 10336 * 4;   // 41344 bytes (max of yfwd 36864, rk 41344)
    cudaFuncSetAttribute(k_epilogue, cudaFuncAttributeMaxDynamicSharedMemorySize, epi_smem);
    cudaFuncSetAttribute(k_yfwd_rk, cudaFuncAttributeMaxDynamicSharedMemorySize, yr_smem);

    k_basis<<<9, 256>>>();
    k_inproj<<<8192, 256>>>(x, W_in, b_in);
    for (int l = 0; l < 4; l++) {
        int srcA = (l % 2 == 0) ? 1 : 0;
        k_yfwd_rk<<<3584, 256, yr_smem>>>(Pc + (size_t)l * 262144,
                                          Qc + (size_t)l * 262144);
        k_xfwd<<<512, 288>>>();
        k_mix<<<576, 256>>>();
        k_inv<<<512, 256, 36864>>>();
        k_epilogue<<<8192, 256, epi_smem>>>(srcA, cw + (size_t)l * 4096,
                                            cb + (size_t)l * 64, l < 3 ? 1 : 0);
    }
    k_outproj<<<dim3(1024, 2), 256>>>(W_out, b_out, out);
}